// round 15
// baseline (speedup 1.0000x reference)
#include <cuda_runtime.h>
#include <math.h>

// Problem constants
#define Bc   2
#define Ac   4
#define Cc   3
#define HWc  1024
#define Nc   4096              // H*W*A
#define BNc  (Bc*Nc)           // 8192 rows
#define LOG2E 1.4426950408889634f

#define JCH  32                // j chunks per batch
#define JPW  128               // j per chunk (= 32 pixels x 4 anchors)

// Scratch (device globals — no allocation allowed)
// Per (row, chunk): {ls0,ls1,ls2,ac0},{ac1,ac2,-,-}; row-major
__device__ float4 g_part[BNc*JCH*2];
__device__ unsigned int g_cnt[32];   // per row-block completion counters (wrap -> replay-safe)

__device__ __forceinline__ float ex2f(float x) {
    float y; asm("ex2.approx.f32 %0, %1;" : "=f"(y) : "f"(x)); return y;
}
__device__ __forceinline__ float warpSum(float v) {
    #pragma unroll
    for (int o = 16; o; o >>= 1) v += __shfl_xor_sync(0xffffffffu, v, o);
    return v;
}

__device__ __forceinline__ float4 decode_box(const float* __restrict__ d, float& area) {
    float x = d[0], y = d[1], d0 = d[3], d1 = d[4], rot = d[6];
    const float PIf  = 3.14159265358979323846f;
    const float PI4f = 0.78539816339744830962f;
    float k = floorf(rot / PIf + 0.5f);
    float normed = fabsf(rot - k * PIf);
    bool sw = normed > PI4f;
    float w = sw ? d1 : d0;
    float h = sw ? d0 : d1;
    area = w * h;
    return make_float4(x - 0.5f * w, y - 0.5f * h, x + 0.5f * w, y + 0.5f * h);
}

// ---- Single fused kernel ----
// Blocks 0..1023: compute tiles (rb = 256-row block [0..31], ch = 128-j chunk [0..31]).
//   The last-finishing block of each rb also reduces+writes that rb's 256 outputs.
// Blocks 1024..1097: pass-through copies.
#define BBOX_F4 14336   // 2*28*1024 /4
#define PP_F4   4608    // 2*9*1024  /4
__global__ __launch_bounds__(256) void main_kernel(
    float* __restrict__ out,
    const float* __restrict__ scores, const float* __restrict__ pp,
    const float* __restrict__ decoded,
    const float4* __restrict__ bboxv, const float4* __restrict__ ppv,
    float4* __restrict__ out_bbox, float4* __restrict__ out_pp)
{
    int tid = threadIdx.x;

    if (blockIdx.x >= 32 * JCH) {            // copy blocks
        int idx = (blockIdx.x - 32 * JCH) * 256 + tid;
        if (idx < BBOX_F4) out_bbox[idx] = bboxv[idx];
        else               out_pp[idx - BBOX_F4] = ppv[idx - BBOX_F4];
        return;
    }

    __shared__ float4 sbox[JPW];             // per anchor j: box
    __shared__ float4 sae[JPW];              // per anchor j: {area, e0, e1, e2}
    __shared__ float4 sp1[JPW / 4];          // per pixel: {p1x, p1y, p1z, -}

    int rb  = blockIdx.x & 31;               // row block 0..31 (0-15: b=0, 16-31: b=1)
    int ch  = blockIdx.x >> 5;               // chunk 0..31
    int row = (rb << 8) + tid;               // 0..8191 (single batch per block)
    int b   = row >> 12;
    int i   = row & (Nc - 1);

    const float* sb = scores + b * (Ac * Cc * HWc);
    const float* pb = pp     + b * (Cc * 3 * HWc);

    // Stage j tile: threads 0..127 stage one anchor each; 0..31 also stage pixel p1
    if (tid < JPW) {
        int jg = (b << 12) + ch * JPW + tid; // global row index of j
        int jl = jg & (Nc - 1);
        float areaJ;
        float4 bj = decode_box(decoded + (size_t)jg * 7, areaJ);
        int hw = jl >> 2, a = jl & 3;
        float e0 = expf(sb[(a * Cc + 0) * HWc + hw]);   // unnormalized softmax numerator
        float e1 = expf(sb[(a * Cc + 1) * HWc + hw]);
        float e2 = expf(sb[(a * Cc + 2) * HWc + hw]);
        sbox[tid] = bj;
        sae[tid]  = make_float4(areaJ, e0, e1, e2);
        if (tid < JPW / 4) {
            int hwp = ch * (JPW / 4) + tid;  // pixel index of this group
            sp1[tid] = make_float4(pb[(0 * 3 + 1) * HWc + hwp],
                                   pb[(1 * 3 + 1) * HWc + hwp],
                                   pb[(2 * 3 + 1) * HWc + hwp], 0.f);
        }
    }
    __syncthreads();

    // Row-resident state (each thread decodes its own row)
    int hwI = i >> 2;
    float ai;
    float4 bb = decode_box(decoded + (size_t)row * 7, ai);
    float p00 = pb[(0 * 3 + 0) * HWc + hwI] * LOG2E;
    float p01 = pb[(1 * 3 + 0) * HWc + hwI] * LOG2E;
    float p02 = pb[(2 * 3 + 0) * HWc + hwI] * LOG2E;

    float ls0 = 0.f, ls1 = 0.f, ls2 = 0.f;
    float ac0 = 0.f, ac1 = 0.f, ac2 = 0.f;

    // Pixel-factored inner loop: rank-1 term exp2(p0*p1) shared by 4 anchors
    #pragma unroll 4
    for (int px = 0; px < JPW / 4; px++) {
        int j4 = px << 2;
        float4 pj = sp1[px];
        float et0 = ex2f(p00 * pj.x);        // exp2(p0_c * p1_c * log2e)
        float et1 = ex2f(p01 * pj.y);
        float et2 = ex2f(p02 * pj.z);
        float siou = 0.f, w0 = 0.f, w1 = 0.f, w2 = 0.f;
        #pragma unroll
        for (int a = 0; a < 4; a++) {
            float4 bj = sbox[j4 + a];
            float4 ae = sae[j4 + a];         // {area, e0, e1, e2}
            float lx = fmaxf(bb.x, bj.x);
            float ly = fmaxf(bb.y, bj.y);
            float rx = fminf(bb.z, bj.z);
            float ry = fminf(bb.w, bj.w);
            float w  = fmaxf(rx - lx, 0.f);
            float h  = fmaxf(ry - ly, 0.f);
            float inter = w * h * LOG2E;
            float uni   = (ai + ae.x);                // union = ai+aj-inter
            float rcu   = __frcp_rn(fmaf(w, -h, uni));// MUFU.RCP(union)
            float ei    = ex2f(inter * rcu);          // exp2(iou*log2e)
            siou += ei;
            w0 = fmaf(ei, ae.y, w0);
            w1 = fmaf(ei, ae.z, w1);
            w2 = fmaf(ei, ae.w, w2);
        }
        ls0 = fmaf(et0, siou, ls0);  ac0 = fmaf(et0, w0, ac0);
        ls1 = fmaf(et1, siou, ls1);  ac1 = fmaf(et1, w1, ac1);
        ls2 = fmaf(et2, siou, ls2);  ac2 = fmaf(et2, w2, ac2);
    }

    size_t p = ((size_t)row * JCH + ch) * 2;
    g_part[p]     = make_float4(ls0, ls1, ls2, ac0);
    g_part[p + 1] = make_float4(ac1, ac2, 0.f, 0.f);

    // ---- Completion protocol: last block of this rb finalizes its 256 rows ----
    __threadfence();                         // release partials (all threads)
    __shared__ unsigned s_old;
    __syncthreads();
    if (tid == 0) s_old = atomicInc(&g_cnt[rb], JCH - 1);  // wraps -> replay-safe
    __syncthreads();
    if (s_old != JCH - 1) return;            // uniform per block
    __threadfence();                         // acquire others' partials

    // Recompute S_b per class: Sum_j exp(score_j) over all 4096 j (block-reduced)
    float s0 = 0.f, s1 = 0.f, s2 = 0.f;
    #pragma unroll
    for (int k = 0; k < 16; k++) {
        int j = (k << 8) + tid;
        int hw = j >> 2, a = j & 3;
        s0 += expf(sb[(a * Cc + 0) * HWc + hw]);
        s1 += expf(sb[(a * Cc + 1) * HWc + hw]);
        s2 += expf(sb[(a * Cc + 2) * HWc + hw]);
    }
    s0 = warpSum(s0); s1 = warpSum(s1); s2 = warpSum(s2);
    __shared__ float srd[3][8];
    int w2i = tid >> 5, l2i = tid & 31;
    if (l2i == 0) { srd[0][w2i] = s0; srd[1][w2i] = s1; srd[2][w2i] = s2; }
    __syncthreads();
    float S0 = 0.f, S1 = 0.f, S2 = 0.f;
    #pragma unroll
    for (int k = 0; k < 8; k++) { S0 += srd[0][k]; S1 += srd[1][k]; S2 += srd[2][k]; }

    // Reduce this thread's row over all 32 chunks (L2-resident partials, ld.cg)
    float L0 = 0.f, L1 = 0.f, L2 = 0.f, A0 = 0.f, A1 = 0.f, A2 = 0.f;
    const float4* gp = g_part + (size_t)row * JCH * 2;
    #pragma unroll 8
    for (int c2 = 0; c2 < JCH; c2++) {
        float4 u = __ldcg(gp + c2 * 2);
        float4 v = __ldcg(gp + c2 * 2 + 1);
        L0 += u.x; L1 += u.y; L2 += u.z;
        A0 += u.w; A1 += v.x; A2 += v.y;
    }
    int a = i & 3, hw = i >> 2;
    float* ob = out + b * (Ac * Cc * HWc);
    ob[(a * Cc + 0) * HWc + hw] = A0 / (L0 * S0);
    ob[(a * Cc + 1) * HWc + hw] = A1 / (L1 * S1);
    ob[(a * Cc + 2) * HWc + hw] = A2 / (L2 * S2);
}

extern "C" void kernel_launch(void* const* d_in, const int* in_sizes, int n_in,
                              void* d_out, int out_size) {
    const float* scores  = (const float*)d_in[0];  // (2,12,32,32)
    const float* bbox    = (const float*)d_in[1];  // (2,28,32,32)
    const float* pp      = (const float*)d_in[2];  // (2,9,32,32)
    const float* decoded = (const float*)d_in[3];  // (2,4096,7)
    float* out = (float*)d_out;

    float4* out_bbox = (float4*)(out + Bc * Ac * Cc * HWc);
    float4* out_pp   = (float4*)(out + Bc * Ac * Cc * HWc + Bc * Ac * 7 * HWc);

    // 1024 compute tiles + 74 copy blocks; reduction fused via last-block protocol
    main_kernel<<<32 * JCH + 74, 256>>>(out, scores, pp, decoded,
                                        (const float4*)bbox, (const float4*)pp,
                                        out_bbox, out_pp);
}

// round 17
// speedup vs baseline: 1.1189x; 1.1189x over previous
#include <cuda_runtime.h>
#include <math.h>

// Problem constants
#define Bc   2
#define Ac   4
#define Cc   3
#define HWc  1024
#define Nc   4096              // H*W*A
#define BNc  (Bc*Nc)           // 8192 rows
#define LOG2E 1.4426950408889634f

#define JCH  32                // j chunks per batch
#define JPW  128               // j per chunk (= 32 pixels x 4 anchors)

// Scratch (device globals — no allocation allowed)
// Per (row, chunk): {ls0,ls1,ls2,ac0},{ac1,ac2,-,-}; row-major (coalesced epilogue)
__device__ float4 g_part[BNc*JCH*2];
__device__ float4 g_esum[Bc*JCH];    // per (b,chunk): sum of e_j per class (.x/.y/.z)

__device__ __forceinline__ float ex2f(float x) {
    float y; asm("ex2.approx.f32 %0, %1;" : "=f"(y) : "f"(x)); return y;
}
__device__ __forceinline__ float warpSum(float v) {
    #pragma unroll
    for (int o = 16; o; o >>= 1) v += __shfl_xor_sync(0xffffffffu, v, o);
    return v;
}

__device__ __forceinline__ float4 decode_box(const float* __restrict__ d, float& area) {
    float x = d[0], y = d[1], d0 = d[3], d1 = d[4], rot = d[6];
    const float PIf  = 3.14159265358979323846f;
    const float PI4f = 0.78539816339744830962f;
    float k = floorf(rot / PIf + 0.5f);
    float normed = fabsf(rot - k * PIf);
    bool sw = normed > PI4f;
    float w = sw ? d1 : d0;
    float h = sw ? d0 : d1;
    area = w * h;
    return make_float4(x - 0.5f * w, y - 0.5f * h, x + 0.5f * w, y + 0.5f * h);
}

// ---- Main kernel: fully self-staged; et-table precomputed per block ----
// Blocks 0..1023: compute tiles (rb = 256-row block [0..31], ch = 128-j chunk [0..31]).
// Blocks 1024..1097: pass-through copies (tail filler).
#define BBOX_F4 14336   // 2*28*1024 /4
#define PP_F4   4608    // 2*9*1024  /4
__global__ __launch_bounds__(256) void main_kernel(
    const float* __restrict__ scores, const float* __restrict__ pp,
    const float* __restrict__ decoded,
    const float4* __restrict__ bboxv, const float4* __restrict__ ppv,
    float4* __restrict__ out_bbox, float4* __restrict__ out_pp)
{
    int tid = threadIdx.x;

    if (blockIdx.x >= 32 * JCH) {            // copy blocks
        int idx = (blockIdx.x - 32 * JCH) * 256 + tid;
        if (idx < BBOX_F4) out_bbox[idx] = bboxv[idx];
        else               out_pp[idx - BBOX_F4] = ppv[idx - BBOX_F4];
        return;
    }

    __shared__ float4 sbox[JPW];             // per anchor j: box
    __shared__ float4 sae[JPW];              // per anchor j: {area, e0, e1, e2}
    __shared__ float4 sp1[JPW / 4];          // per j-pixel: {p1x, p1y, p1z, -}
    __shared__ float4 s_et[(JPW / 4) * 64];  // [jpx][rowpx]: exp2(p0_c*p1_c*l2e) per class (32KB)

    int rb  = blockIdx.x & 31;               // row block 0..31 (0-15: b=0, 16-31: b=1)
    int ch  = blockIdx.x >> 5;               // chunk 0..31
    int row = (rb << 8) + tid;               // 0..8191 (single batch per block)
    int b   = row >> 12;
    int i   = row & (Nc - 1);

    const float* sb = scores + b * (Ac * Cc * HWc);
    const float* pb = pp     + b * (Cc * 3 * HWc);

    // Stage j tile: threads 0..127 stage one anchor each; 0..31 also stage pixel p1
    if (tid < JPW) {
        int jg = (b << 12) + ch * JPW + tid; // global row index of j
        int jl = jg & (Nc - 1);
        float areaJ;
        float4 bj = decode_box(decoded + (size_t)jg * 7, areaJ);
        int hw = jl >> 2, a = jl & 3;
        float e0 = expf(sb[(a * Cc + 0) * HWc + hw]);   // unnormalized softmax numerator
        float e1 = expf(sb[(a * Cc + 1) * HWc + hw]);
        float e2 = expf(sb[(a * Cc + 2) * HWc + hw]);
        sbox[tid] = bj;
        sae[tid]  = make_float4(areaJ, e0, e1, e2);
        if (tid < JPW / 4) {
            int hwp = ch * (JPW / 4) + tid;  // j-pixel index (in-batch)
            sp1[tid] = make_float4(pb[(0 * 3 + 1) * HWc + hwp],
                                   pb[(1 * 3 + 1) * HWc + hwp],
                                   pb[(2 * 3 + 1) * HWc + hwp], 0.f);
        }
    }
    __syncthreads();

    // Designated blocks publish per-chunk e-sums (rb==0 for b=0, rb==16 for b=1)
    if (((rb & 15) == 0) && tid < 32) {
        float s0 = 0.f, s1 = 0.f, s2 = 0.f;
        #pragma unroll
        for (int k = 0; k < JPW / 32; k++) {
            float4 ev = sae[tid + 32 * k];
            s0 += ev.y; s1 += ev.z; s2 += ev.w;
        }
        s0 = warpSum(s0); s1 = warpSum(s1); s2 = warpSum(s2);
        if (tid == 0) g_esum[b * JCH + ch] = make_float4(s0, s1, s2, 0.f);
    }

    // et-table precompute: 64 row-pixels x 32 j-pixels x 3 classes, 24 EX2/thread.
    // Thread t handles rowpx = t>>2, j-pixels [(t&3)*8, +8).
    {
        int rpx = tid >> 2;                  // 0..63 local row-pixel
        int hw0 = ((rb & 15) << 6) + rpx;    // IN-BATCH pixel (FIX: was rb<<6)
        float q0 = pb[(0 * 3 + 0) * HWc + hw0] * LOG2E;
        float q1 = pb[(1 * 3 + 0) * HWc + hw0] * LOG2E;
        float q2 = pb[(2 * 3 + 0) * HWc + hw0] * LOG2E;
        int j0 = (tid & 3) * 8;
        #pragma unroll
        for (int jj = 0; jj < 8; jj++) {
            float4 p1j = sp1[j0 + jj];
            s_et[(j0 + jj) * 64 + rpx] =
                make_float4(ex2f(q0 * p1j.x), ex2f(q1 * p1j.y), ex2f(q2 * p1j.z), 0.f);
        }
    }
    __syncthreads();

    // Row-resident state (each thread decodes its own row)
    float ai;
    float4 bb = decode_box(decoded + (size_t)row * 7, ai);
    int rpx = tid >> 2;

    float ls0 = 0.f, ls1 = 0.f, ls2 = 0.f;
    float ac0 = 0.f, ac1 = 0.f, ac2 = 0.f;

    // Inner loop: per j-pixel group of 4 anchors; et read as one LDS.128
    // (warp reads 8 consecutive float4 -> 128B contiguous, conflict-free broadcast)
    #pragma unroll 4
    for (int px = 0; px < JPW / 4; px++) {
        int j4 = px << 2;
        float4 et4 = s_et[(px << 6) + rpx];
        float siou = 0.f, w0 = 0.f, w1 = 0.f, w2 = 0.f;
        #pragma unroll
        for (int a = 0; a < 4; a++) {
            float4 bj = sbox[j4 + a];
            float4 ae = sae[j4 + a];         // {area, e0, e1, e2}
            float lx = fmaxf(bb.x, bj.x);
            float ly = fmaxf(bb.y, bj.y);
            float rx = fminf(bb.z, bj.z);
            float ry = fminf(bb.w, bj.w);
            float w  = fmaxf(rx - lx, 0.f);
            float h  = fmaxf(ry - ly, 0.f);
            float inter = w * h * LOG2E;
            float uni   = (ai + ae.x);                // union = ai+aj-inter
            float rcu   = __frcp_rn(fmaf(w, -h, uni));// MUFU.RCP(union)
            float ei    = ex2f(inter * rcu);          // exp2(iou*log2e)
            siou += ei;
            w0 = fmaf(ei, ae.y, w0);
            w1 = fmaf(ei, ae.z, w1);
            w2 = fmaf(ei, ae.w, w2);
        }
        ls0 = fmaf(et4.x, siou, ls0);  ac0 = fmaf(et4.x, w0, ac0);
        ls1 = fmaf(et4.y, siou, ls1);  ac1 = fmaf(et4.y, w1, ac1);
        ls2 = fmaf(et4.z, siou, ls2);  ac2 = fmaf(et4.z, w2, ac2);
    }

    size_t p = ((size_t)row * JCH + ch) * 2;
    g_part[p]     = make_float4(ls0, ls1, ls2, ac0);
    g_part[p + 1] = make_float4(ac1, ac2, 0.f, 0.f);
}

// ---- Epilogue: warp per row, lane = chunk; fully coalesced 1KB row reads ----
__global__ __launch_bounds__(256) void epilogue_kernel(float* __restrict__ out) {
    int wid  = threadIdx.x >> 5, lane = threadIdx.x & 31;
    int row  = blockIdx.x * 8 + wid;            // 0..8191
    int b = row >> 12, i = row & (Nc - 1);

    size_t p = ((size_t)row * JCH + lane) * 2;
    float4 u = g_part[p];
    float4 v = g_part[p + 1];
    float4 es = g_esum[b * JCH + lane];

    float ls0 = warpSum(u.x), ls1 = warpSum(u.y), ls2 = warpSum(u.z);
    float ac0 = warpSum(u.w), ac1 = warpSum(v.x), ac2 = warpSum(v.y);
    float S0  = warpSum(es.x), S1 = warpSum(es.y), S2 = warpSum(es.z);

    if (lane == 0) {
        int a = i & 3, hw = i >> 2;
        float* ob = out + b * (Ac * Cc * HWc);
        ob[(a * Cc + 0) * HWc + hw] = ac0 / (ls0 * S0);
        ob[(a * Cc + 1) * HWc + hw] = ac1 / (ls1 * S1);
        ob[(a * Cc + 2) * HWc + hw] = ac2 / (ls2 * S2);
    }
}

extern "C" void kernel_launch(void* const* d_in, const int* in_sizes, int n_in,
                              void* d_out, int out_size) {
    const float* scores  = (const float*)d_in[0];  // (2,12,32,32)
    const float* bbox    = (const float*)d_in[1];  // (2,28,32,32)
    const float* pp      = (const float*)d_in[2];  // (2,9,32,32)
    const float* decoded = (const float*)d_in[3];  // (2,4096,7)
    float* out = (float*)d_out;

    float4* out_bbox = (float4*)(out + Bc * Ac * Cc * HWc);
    float4* out_pp   = (float4*)(out + Bc * Ac * Cc * HWc + Bc * Ac * 7 * HWc);

    // 1024 compute tiles + 74 copy blocks (multi-wave self-balancing layout)
    main_kernel<<<32 * JCH + 74, 256>>>(scores, pp, decoded,
                                        (const float4*)bbox, (const float4*)pp,
                                        out_bbox, out_pp);

    // 8192 rows, 8 warp-rows per block -> 1024 blocks
    epilogue_kernel<<<BNc / 8, 256>>>(out);
}